// round 10
// baseline (speedup 1.0000x reference)
#include <cuda_runtime.h>
#include <cstdint>

// Problem shape (fixed by the reference): B=4, N=M=8192, D=3, fp32.
// Exact NN via uniform grid (G=16): branch-free 3x3x3 fast path + rare pruned fallback.
#define BATCH   4
#define NPTS    8192
#define G       16
#define NC      (G * G * G)            // 4096 cells per grid
#define NGRIDS  (2 * BATCH)            // 8: [0..3]=y content per batch, [4..7]=x content
#define TOTQ    (2 * BATCH * NPTS)     // 65536 queries
#define GS      1.6f                   // G / 10
#define H       0.625f                 // 10 / G (exact in fp32)
#define LOV     (-5.0f)
#define EPS     1e-3f
#define DONE2   0.378f                 // (H - 0.01)^2 fast-path acceptance bound
#define SUMA_CTAS 64

// Static scratch (zero-initialized at load; g_cnt re-zeroed by sumA each replay).
__device__ int    g_cnt[NGRIDS * NC];
__device__ int    g_start[NGRIDS * NC];
__device__ int    g_end[NGRIDS * NC];
__device__ int    g_cursor[NGRIDS * NC];
__device__ float4 g_pts[NGRIDS * NPTS];
__device__ float  g_res[TOTQ];
__device__ float  g_part[SUMA_CTAS];

__device__ __forceinline__ int cellco(float v) {
    int c = (int)((v - LOV) * GS);
    return min(max(c, 0), G - 1);
}

// ---------------- 1. count points per cell ----------------
__global__ void count_kernel(const float* __restrict__ x, const float* __restrict__ y) {
    int tid = blockIdx.x * blockDim.x + threadIdx.x;   // 65536
    int i = tid & (NPTS - 1);
    int b = (tid >> 13) & 3;
    int s = tid >> 15;                                  // 0: content y, 1: content x
    const float* src = s ? x : y;
    const float* p = src + ((size_t)b * NPTS + i) * 3;
    int cell = (cellco(p[2]) * G + cellco(p[1])) * G + cellco(p[0]);
    atomicAdd(&g_cnt[(s * BATCH + b) * NC + cell], 1);
}

// ---------------- 2. per-grid scan: starts, ends, cursors (one block per grid) ----------------
__global__ void scan_kernel() {
    __shared__ int sm[1024];
    int t = threadIdx.x;
    int base = blockIdx.x * NC + t * 4;
    int c0 = g_cnt[base], c1 = g_cnt[base + 1], c2 = g_cnt[base + 2], c3 = g_cnt[base + 3];
    int tot = c0 + c1 + c2 + c3;
    sm[t] = tot;
    __syncthreads();
    for (int off = 1; off < 1024; off <<= 1) {
        int v = (t >= off) ? sm[t - off] : 0;
        __syncthreads();
        sm[t] += v;
        __syncthreads();
    }
    int e = sm[t] - tot;
    int s0 = e, s1 = e + c0, s2 = s1 + c1, s3 = s2 + c2;
    g_start[base] = s0;   g_end[base] = s1;        g_cursor[base] = s0;
    g_start[base+1] = s1; g_end[base+1] = s2;      g_cursor[base+1] = s1;
    g_start[base+2] = s2; g_end[base+2] = s3;      g_cursor[base+2] = s2;
    g_start[base+3] = s3; g_end[base+3] = s3 + c3; g_cursor[base+3] = s3;
}

// ---------------- 3. scatter points into CSR order ----------------
__global__ void scatter_kernel(const float* __restrict__ x, const float* __restrict__ y) {
    int tid = blockIdx.x * blockDim.x + threadIdx.x;
    int i = tid & (NPTS - 1);
    int b = (tid >> 13) & 3;
    int s = tid >> 15;
    const float* src = s ? x : y;
    const float* p = src + ((size_t)b * NPTS + i) * 3;
    float p0 = p[0], p1 = p[1], p2 = p[2];
    int cell = (cellco(p2) * G + cellco(p1)) * G + cellco(p0);
    int g = s * BATCH + b;
    int pos = atomicAdd(&g_cursor[g * NC + cell], 1);
    g_pts[g * NPTS + pos] = make_float4(p0, p1, p2, 0.0f);
}

// ---------------- 4. query ----------------
// Rare-tail fallback: pruned cube expansion starting at ring 2 (ring<=1 already scanned).
__device__ __noinline__ float query_fallback(const int* __restrict__ st,
                                             const int* __restrict__ en,
                                             const float4* __restrict__ pp,
                                             float q0, float q1, float q2,
                                             int cx, int cy, int cz, float best) {
    for (int r = 2; ; r++) {
        int zl = max(cz - r, 0), zh = min(cz + r, G - 1);
        int yl = max(cy - r, 0), yh = min(cy + r, G - 1);
        for (int z = zl; z <= zh; z++) {
            float dzd = 0.0f;
            if (z < cz)      dzd = q2 - (LOV + (float)(z + 1) * H);
            else if (z > cz) dzd = (LOV + (float)z * H) - q2;
            dzd = fmaxf(dzd - EPS, 0.0f);
            float dz2 = dzd * dzd;
            if (dz2 >= best) continue;
            for (int yy = yl; yy <= yh; yy++) {
                // skip cells already scanned by the fast path (Chebyshev <= 1)
                bool inner = (z >= cz - 1 && z <= cz + 1 && yy >= cy - 1 && yy <= cy + 1);
                float dyd = 0.0f;
                if (yy < cy)      dyd = q1 - (LOV + (float)(yy + 1) * H);
                else if (yy > cy) dyd = (LOV + (float)yy * H) - q1;
                dyd = fmaxf(dyd - EPS, 0.0f);
                float rb = fmaf(dyd, dyd, dz2);
                if (rb >= best) continue;
                float rad = sqrtf(best - rb);
                int xl = max(cellco(q0 - rad), max(cx - r, 0));
                int xh = min(cellco(q0 + rad), min(cx + r, G - 1));
                if (inner) {
                    // split around the already-scanned x in [cx-1, cx+1]
                    int rowb = (z * G + yy) * G;
                    int al = xl, ah = min(xh, cx - 2);
                    for (int seg = 0; seg < 2; seg++) {
                        if (al <= ah) {
                            int j0 = st[rowb + al], j1 = en[rowb + ah];
                            for (int j = j0; j < j1; j++) {
                                float4 p = pp[j];
                                float d0 = q0 - p.x, d1 = q1 - p.y, d2 = q2 - p.z;
                                best = fminf(best, fmaf(d0, d0, fmaf(d1, d1, d2 * d2)));
                            }
                        }
                        al = max(xl, cx + 2); ah = xh;
                    }
                } else {
                    if (xl > xh) continue;
                    int rowb = (z * G + yy) * G;
                    int j0 = st[rowb + xl], j1 = en[rowb + xh];
                    for (int j = j0; j < j1; j++) {
                        float4 p = pp[j];
                        float d0 = q0 - p.x, d1 = q1 - p.y, d2 = q2 - p.z;
                        best = fminf(best, fmaf(d0, d0, fmaf(d1, d1, d2 * d2)));
                    }
                }
            }
        }
        float bnd = (float)r * H - 0.01f;
        if (best <= bnd * bnd || r >= G - 1) break;
    }
    return best;
}

__global__ void __launch_bounds__(256)
query_kernel(const float* __restrict__ x, const float* __restrict__ y) {
    int tid = blockIdx.x * blockDim.x + threadIdx.x;   // 65536
    int i = tid & (NPTS - 1);
    int b = (tid >> 13) & 3;
    int s = tid >> 15;                   // 0: x queries -> y grid; 1: y queries -> x grid
    const float* src = s ? y : x;
    const float* q = src + ((size_t)b * NPTS + i) * 3;
    float q0 = q[0], q1 = q[1], q2 = q[2];
    int g = s ? (BATCH + b) : b;

    const int*    st = g_start + g * NC;
    const int*    en = g_end   + g * NC;
    const float4* pp = g_pts   + g * NPTS;

    int cx = cellco(q0), cy = cellco(q1), cz = cellco(q2);

    // ---- fast path: branch-free 3x3x3 cube, all 18 range loads issued up front ----
    int xl = max(cx - 1, 0), xh = min(cx + 1, G - 1);
    int zs0 = max(cz - 1, 0), zs2 = min(cz + 1, G - 1);
    int ys0 = max(cy - 1, 0), ys2 = min(cy + 1, G - 1);
    int zs[3] = {zs0, cz, zs2};
    int ys[3] = {ys0, cy, ys2};

    int j0[9], j1[9];
#pragma unroll
    for (int a = 0; a < 3; a++)
#pragma unroll
        for (int c = 0; c < 3; c++) {
            int rowb = (zs[a] * G + ys[c]) * G;
            j0[a * 3 + c] = st[rowb + xl];
            j1[a * 3 + c] = en[rowb + xh];
        }

    float best = 3.0e38f;
#pragma unroll
    for (int r9 = 0; r9 < 9; r9++) {
        for (int j = j0[r9]; j < j1[r9]; j++) {
            float4 p = pp[j];
            float d0 = q0 - p.x, d1 = q1 - p.y, d2 = q2 - p.z;
            best = fminf(best, fmaf(d0, d0, fmaf(d1, d1, d2 * d2)));
        }
    }

    // Unscanned cells are Chebyshev >= 2 away: distance >= H (minus fp slack).
    if (best > DONE2)
        best = query_fallback(st, en, pp, q0, q1, q2, cx, cy, cz, best);

    g_res[tid] = fmaxf(best, 0.0f);
}

// ---------------- 5a. 64-CTA deterministic partial sums (+ re-zero counts) ----------------
__global__ void sumA_kernel() {
    __shared__ float red[256];
    const float4* gp = (const float4*)g_res;
    float4 v = gp[blockIdx.x * 256 + threadIdx.x];
    float ss = (v.x + v.y) + (v.z + v.w);
    ((int2*)g_cnt)[blockIdx.x * 256 + threadIdx.x] = make_int2(0, 0);  // reset counts
    red[threadIdx.x] = ss;
    __syncthreads();
    for (int k = 128; k > 0; k >>= 1) {
        if (threadIdx.x < k) red[threadIdx.x] += red[threadIdx.x + k];
        __syncthreads();
    }
    if (threadIdx.x == 0) g_part[blockIdx.x] = red[0];
}

// ---------------- 5b. combine partials + scale ----------------
__global__ void sumB_kernel(float* __restrict__ out) {
    __shared__ float red[SUMA_CTAS];
    red[threadIdx.x] = g_part[threadIdx.x];
    __syncthreads();
    for (int k = SUMA_CTAS / 2; k > 0; k >>= 1) {
        if (threadIdx.x < k) red[threadIdx.x] += red[threadIdx.x + k];
        __syncthreads();
    }
    if (threadIdx.x == 0)
        out[0] = red[0] * (1.0f / (float)(BATCH * NPTS));
}

extern "C" void kernel_launch(void* const* d_in, const int* in_sizes, int n_in,
                              void* d_out, int out_size) {
    const float* x = (const float*)d_in[0];
    const float* y = (const float*)d_in[1];
    float* out = (float*)d_out;
    (void)in_sizes; (void)n_in; (void)out_size;

    count_kernel<<<TOTQ / 256, 256>>>(x, y);
    scan_kernel<<<NGRIDS, 1024>>>();
    scatter_kernel<<<TOTQ / 256, 256>>>(x, y);
    query_kernel<<<TOTQ / 256, 256>>>(x, y);
    sumA_kernel<<<SUMA_CTAS, 256>>>();
    sumB_kernel<<<1, SUMA_CTAS>>>(out);
}